// round 10
// baseline (speedup 1.0000x reference)
#include <cuda_runtime.h>
#include <cstdint>

#define UNITS   2048
#define IN_DIM  512
#define TSTEPS  8192
#define NCTA    128
#define SCAN_THREADS 256

// 64 MB staging buffer for xin = x @ wax^T + ba
__device__ float g_xin[(size_t)TSTEPS * UNITS];
// DENSE per-CTA step flags: 128 x 4B = 4 cache lines. Writers use plain
// st.release (no atomics); pollers read one full line per warp, coalesced.
__device__ unsigned g_flags[NCTA];

__device__ __forceinline__ unsigned ld_relaxed_gpu(const unsigned* p) {
    unsigned v;
    asm volatile("ld.relaxed.gpu.u32 %0, [%1];" : "=r"(v) : "l"(p) : "memory");
    return v;
}
__device__ __forceinline__ void st_release_gpu(unsigned* p, unsigned v) {
    asm volatile("st.release.gpu.u32 [%0], %1;" :: "l"(p), "r"(v) : "memory");
}
__device__ __forceinline__ void fence_acq_rel_gpu() {
    asm volatile("fence.acq_rel.gpu;" ::: "memory");
}
__device__ __forceinline__ unsigned long long ffma2(
    unsigned long long a, unsigned long long b, unsigned long long c) {
    unsigned long long d;
    asm("fma.rn.f32x2 %0, %1, %2, %3;" : "=l"(d) : "l"(a), "l"(b), "l"(c));
    return d;
}
__device__ __forceinline__ unsigned long long packf2(float x, float y) {
    unsigned long long p;
    asm("mov.b64 %0, {%1, %2};" : "=l"(p) : "f"(x), "f"(y));
    return p;
}
__device__ __forceinline__ float pair_sum(unsigned long long p) {
    float lo, hi;
    asm("mov.b64 {%0, %1}, %2;" : "=f"(lo), "=f"(hi) : "l"(p));
    return lo + hi;
}

// ---------------------------------------------------------------------------
// Phase 1: xin[t][u] = sum_d x[t][d] * wax[u][d] + ba[u]
// blockIdx.y==0 blocks also zero the flags (every replay, before scan).
// ---------------------------------------------------------------------------
__global__ __launch_bounds__(256) void xin_gemm_kernel(
    const float* __restrict__ x,     // [8192][512]
    const float* __restrict__ wax,   // [2048][512]
    const float* __restrict__ ba)    // [2048]
{
    if (blockIdx.y == 0) {
        int idx = blockIdx.x * 256 + threadIdx.x;
        if (idx < NCTA)
            g_flags[idx] = 0u;
    }

    __shared__ float As[16][128 + 4];
    __shared__ float Bs[16][64 + 4];

    const int tid = threadIdx.x;
    const int bm = blockIdx.y * 128;
    const int bn = blockIdx.x * 64;
    const int tx = tid & 15;
    const int ty = tid >> 4;

    float acc[8][4];
#pragma unroll
    for (int i = 0; i < 8; i++)
#pragma unroll
        for (int j = 0; j < 4; j++) acc[i][j] = 0.f;

    const int lr = tid >> 2;
    const int lc = (tid & 3) * 4;

    for (int k0 = 0; k0 < IN_DIM; k0 += 16) {
        float4 a0 = *(const float4*)&x[(size_t)(bm + lr) * IN_DIM + k0 + lc];
        float4 a1 = *(const float4*)&x[(size_t)(bm + lr + 64) * IN_DIM + k0 + lc];
        float4 b0 = *(const float4*)&wax[(size_t)(bn + lr) * IN_DIM + k0 + lc];

        As[lc + 0][lr] = a0.x; As[lc + 1][lr] = a0.y;
        As[lc + 2][lr] = a0.z; As[lc + 3][lr] = a0.w;
        As[lc + 0][lr + 64] = a1.x; As[lc + 1][lr + 64] = a1.y;
        As[lc + 2][lr + 64] = a1.z; As[lc + 3][lr + 64] = a1.w;
        Bs[lc + 0][lr] = b0.x; Bs[lc + 1][lr] = b0.y;
        Bs[lc + 2][lr] = b0.z; Bs[lc + 3][lr] = b0.w;
        __syncthreads();

#pragma unroll
        for (int kk = 0; kk < 16; kk++) {
            float4 av0 = *(const float4*)&As[kk][ty * 8];
            float4 av1 = *(const float4*)&As[kk][ty * 8 + 4];
            float4 bv  = *(const float4*)&Bs[kk][tx * 4];
            float a[8] = {av0.x, av0.y, av0.z, av0.w, av1.x, av1.y, av1.z, av1.w};
            float b[4] = {bv.x, bv.y, bv.z, bv.w};
#pragma unroll
            for (int i = 0; i < 8; i++)
#pragma unroll
                for (int j = 0; j < 4; j++)
                    acc[i][j] = fmaf(a[i], b[j], acc[i][j]);
        }
        __syncthreads();
    }

    float4 bav = *(const float4*)&ba[bn + tx * 4];
#pragma unroll
    for (int i = 0; i < 8; i++) {
        float4 c;
        c.x = acc[i][0] + bav.x;
        c.y = acc[i][1] + bav.y;
        c.z = acc[i][2] + bav.z;
        c.w = acc[i][3] + bav.w;
        *(float4*)&g_xin[(size_t)(bm + ty * 8 + i) * UNITS + bn + tx * 4] = c;
    }
}

// ---------------------------------------------------------------------------
// Phase 2: persistent scan (R5 compute skeleton, new barrier transport).
// 128 CTAs x 256 threads; CTA owns 16 rows, warp w owns rows {16c+2w, +1};
// lane holds cols {128k+4l..+3} for both rows (f32x2 packed).
// Per step t>0:
//   warps 0-3: lane l self-polls g_flags[w*32+l] (ONE coalesced 128B line
//   per warp per iteration) until >= t, then fence.acq_rel; warps 4-7 go
//   straight to the barrier.
//   -> __syncthreads -> stage out[t-1] into SMEM -> __syncthreads
//   -> 64 FFMA2/lane (4 chains) -> 10-shfl butterfly -> lane0: tanh x2,
//   8B store to out[t] -> __syncthreads -> tid0: st.release g_flags[cta]=t+1.
// out[] is append-only history: CTA skew is data-safe, flags only gate reads.
// ---------------------------------------------------------------------------
__global__ __launch_bounds__(SCAN_THREADS, 1) void scan_kernel(
    const float* __restrict__ waa,   // [2048][2048]
    float* __restrict__ out)         // [8192][2048]
{
    __shared__ float a_sm[UNITS];
    float4* a_sm4 = (float4*)a_sm;

    const int tid  = threadIdx.x;
    const int lane = tid & 31;
    const int warp = tid >> 5;               // 0..7
    const int cta  = blockIdx.x;             // 0..127
    const int row0 = cta * 16 + warp * 2;

    // Preload weights packed as f32x2
    unsigned long long w0[16][2], w1[16][2];
#pragma unroll
    for (int k = 0; k < 16; k++) {
        float4 f0 = *(const float4*)&waa[(size_t)row0 * UNITS + k * 128 + lane * 4];
        float4 f1 = *(const float4*)&waa[(size_t)(row0 + 1) * UNITS + k * 128 + lane * 4];
        w0[k][0] = packf2(f0.x, f0.y); w0[k][1] = packf2(f0.z, f0.w);
        w1[k][0] = packf2(f1.x, f1.y); w1[k][1] = packf2(f1.z, f1.w);
    }

    // polling warps 0-3: one flag per lane, one cache line per warp
    const unsigned* fpoll = &g_flags[warp * 32 + lane];

    for (int t = 0; t < TSTEPS; t++) {
        float2 xv;
        if (lane == 0)
            xv = *(const float2*)&g_xin[(size_t)t * UNITS + row0];

        if (t > 0) {
            if (warp < 4) {
                const unsigned target = (unsigned)t;
                while (ld_relaxed_gpu(fpoll) < target) { }
                fence_acq_rel_gpu();
            }
            __syncthreads();   // join pollers + non-pollers
            const float4* aprev = (const float4*)(out + (size_t)(t - 1) * UNITS);
            a_sm4[tid]       = aprev[tid];
            a_sm4[tid + 256] = aprev[tid + 256];
        } else {
            a_sm4[tid]       = make_float4(0.f, 0.f, 0.f, 0.f);
            a_sm4[tid + 256] = make_float4(0.f, 0.f, 0.f, 0.f);
        }
        __syncthreads();   // state staged

        // 2 rows x 2048 cols: 64 FFMA2 per lane, 4 independent chains
        unsigned long long acc0a = 0ull, acc0b = 0ull;
        unsigned long long acc1a = 0ull, acc1b = 0ull;
#pragma unroll
        for (int k = 0; k < 16; k++) {
            float4 av = a_sm4[k * 32 + lane];
            unsigned long long pa = packf2(av.x, av.y);
            unsigned long long pb = packf2(av.z, av.w);
            acc0a = ffma2(w0[k][0], pa, acc0a);
            acc0b = ffma2(w0[k][1], pb, acc0b);
            acc1a = ffma2(w1[k][0], pa, acc1a);
            acc1b = ffma2(w1[k][1], pb, acc1b);
        }
        float s0 = pair_sum(acc0a) + pair_sum(acc0b);
        float s1 = pair_sum(acc1a) + pair_sum(acc1b);

#pragma unroll
        for (int off = 16; off; off >>= 1) {
            s0 += __shfl_xor_sync(0xffffffffu, s0, off);
            s1 += __shfl_xor_sync(0xffffffffu, s1, off);
        }

        if (lane == 0) {
            float2 h;
            h.x = tanhf(s0 + xv.x);
            h.y = tanhf(s1 + xv.y);
            *(float2*)&out[(size_t)t * UNITS + row0] = h;
        }

        __syncthreads();   // all rows of out[t] stored before the release
        if (tid == 0)
            st_release_gpu(&g_flags[cta], (unsigned)(t + 1));
    }
}

// ---------------------------------------------------------------------------
extern "C" void kernel_launch(void* const* d_in, const int* in_sizes, int n_in,
                              void* d_out, int out_size) {
    const float* x   = (const float*)d_in[0];   // (1, 8192, 512)
    const float* waa = (const float*)d_in[1];   // (2048, 2048)
    const float* wax = (const float*)d_in[2];   // (2048, 512)
    const float* ba  = (const float*)d_in[3];   // (2048, 1)
    float* out = (float*)d_out;                 // (1, 8192, 2048)

    dim3 grid(UNITS / 64, TSTEPS / 128);        // (32, 64)
    xin_gemm_kernel<<<grid, 256>>>(x, wax, ba); // also zeroes flags

    scan_kernel<<<NCTA, SCAN_THREADS>>>(waa, out);
}

// round 11
// speedup vs baseline: 2.0543x; 2.0543x over previous
#include <cuda_runtime.h>
#include <cstdint>

#define UNITS   2048
#define IN_DIM  512
#define TSTEPS  8192
#define NCTA    128
#define SCAN_THREADS 256

// 64 MB staging buffer for xin = x @ wax^T + ba
__device__ float g_xin[(size_t)TSTEPS * UNITS];
// single counting barrier: each CTA adds 1 per completed step (R5 transport)
__device__ unsigned g_ctr;

__device__ __forceinline__ unsigned ld_relaxed_gpu(const unsigned* p) {
    unsigned v;
    asm volatile("ld.relaxed.gpu.u32 %0, [%1];" : "=r"(v) : "l"(p) : "memory");
    return v;
}
__device__ __forceinline__ void red_release_add(unsigned* p, unsigned v) {
    asm volatile("red.release.gpu.global.add.u32 [%0], %1;"
                 :: "l"(p), "r"(v) : "memory");
}
__device__ __forceinline__ void fence_acq_rel_gpu() {
    asm volatile("fence.acq_rel.gpu;" ::: "memory");
}
__device__ __forceinline__ unsigned long long ffma2(
    unsigned long long a, unsigned long long b, unsigned long long c) {
    unsigned long long d;
    asm("fma.rn.f32x2 %0, %1, %2, %3;" : "=l"(d) : "l"(a), "l"(b), "l"(c));
    return d;
}
__device__ __forceinline__ unsigned long long addf2(
    unsigned long long a, unsigned long long b) {
    unsigned long long d;
    asm("add.rn.f32x2 %0, %1, %2;" : "=l"(d) : "l"(a), "l"(b));
    return d;
}
__device__ __forceinline__ unsigned long long packf2(float x, float y) {
    unsigned long long p;
    asm("mov.b64 %0, {%1, %2};" : "=l"(p) : "f"(x), "f"(y));
    return p;
}
__device__ __forceinline__ void unpackf2(unsigned long long p, float& x, float& y) {
    asm("mov.b64 {%0, %1}, %2;" : "=f"(x), "=f"(y) : "l"(p));
}
__device__ __forceinline__ float pair_sum(unsigned long long p) {
    float lo, hi;
    asm("mov.b64 {%0, %1}, %2;" : "=f"(lo), "=f"(hi) : "l"(p));
    return lo + hi;
}

// ---------------------------------------------------------------------------
// Phase 1: xin[t][u] = sum_d x[t][d] * wax[u][d] + ba[u]
// block (0,0) also resets the scan barrier counter.
// ---------------------------------------------------------------------------
__global__ __launch_bounds__(256) void xin_gemm_kernel(
    const float* __restrict__ x,     // [8192][512]
    const float* __restrict__ wax,   // [2048][512]
    const float* __restrict__ ba)    // [2048]
{
    if (blockIdx.x == 0 && blockIdx.y == 0 && threadIdx.x == 0)
        g_ctr = 0u;

    __shared__ float As[16][128 + 4];
    __shared__ float Bs[16][64 + 4];

    const int tid = threadIdx.x;
    const int bm = blockIdx.y * 128;
    const int bn = blockIdx.x * 64;
    const int tx = tid & 15;
    const int ty = tid >> 4;

    float acc[8][4];
#pragma unroll
    for (int i = 0; i < 8; i++)
#pragma unroll
        for (int j = 0; j < 4; j++) acc[i][j] = 0.f;

    const int lr = tid >> 2;
    const int lc = (tid & 3) * 4;

    for (int k0 = 0; k0 < IN_DIM; k0 += 16) {
        float4 a0 = *(const float4*)&x[(size_t)(bm + lr) * IN_DIM + k0 + lc];
        float4 a1 = *(const float4*)&x[(size_t)(bm + lr + 64) * IN_DIM + k0 + lc];
        float4 b0 = *(const float4*)&wax[(size_t)(bn + lr) * IN_DIM + k0 + lc];

        As[lc + 0][lr] = a0.x; As[lc + 1][lr] = a0.y;
        As[lc + 2][lr] = a0.z; As[lc + 3][lr] = a0.w;
        As[lc + 0][lr + 64] = a1.x; As[lc + 1][lr + 64] = a1.y;
        As[lc + 2][lr + 64] = a1.z; As[lc + 3][lr + 64] = a1.w;
        Bs[lc + 0][lr] = b0.x; Bs[lc + 1][lr] = b0.y;
        Bs[lc + 2][lr] = b0.z; Bs[lc + 3][lr] = b0.w;
        __syncthreads();

#pragma unroll
        for (int kk = 0; kk < 16; kk++) {
            float4 av0 = *(const float4*)&As[kk][ty * 8];
            float4 av1 = *(const float4*)&As[kk][ty * 8 + 4];
            float4 bv  = *(const float4*)&Bs[kk][tx * 4];
            float a[8] = {av0.x, av0.y, av0.z, av0.w, av1.x, av1.y, av1.z, av1.w};
            float b[4] = {bv.x, bv.y, bv.z, bv.w};
#pragma unroll
            for (int i = 0; i < 8; i++)
#pragma unroll
                for (int j = 0; j < 4; j++)
                    acc[i][j] = fmaf(a[i], b[j], acc[i][j]);
        }
        __syncthreads();
    }

    float4 bav = *(const float4*)&ba[bn + tx * 4];
#pragma unroll
    for (int i = 0; i < 8; i++) {
        float4 c;
        c.x = acc[i][0] + bav.x;
        c.y = acc[i][1] + bav.y;
        c.z = acc[i][2] + bav.z;
        c.w = acc[i][3] + bav.w;
        *(float4*)&g_xin[(size_t)(bm + ty * 8 + i) * UNITS + bn + tx * 4] = c;
    }
}

// ---------------------------------------------------------------------------
// Phase 2: persistent scan — R5 transport, staging hop removed.
// 128 CTAs x 256 threads; CTA owns 16 rows, warp w owns rows {16c+2w, +1};
// lane holds cols {128k+4l..+3} for both rows (f32x2 packed, 128 regs).
// Per step t>0:
//   warp0: relaxed-poll single counter (ONE broadcast address, one
//   wavefront per iteration — the only poll shape that doesn't poison the
//   L1tex queue) for 128*t, then one fence.acq_rel (CCTL.IVALL flushes L1)
//   -> __syncthreads -> every warp LDGs the FULL 8KB state directly from
//   out[t-1] (warp-identical addresses: first toucher L2-misses with
//   MLP=16, rest hit L1), pipelined into 64 FFMA2/lane (4 chains)
//   -> packed f32x2 butterfly (10 shfl + 5 add64) -> lane0: +xin (packed),
//   tanh x2, 8B store -> __syncthreads -> tid0: red.release.add(+1).
// ---------------------------------------------------------------------------
__global__ __launch_bounds__(SCAN_THREADS, 1) void scan_kernel(
    const float* __restrict__ waa,   // [2048][2048]
    float* __restrict__ out)         // [8192][2048]
{
    const int tid  = threadIdx.x;
    const int lane = tid & 31;
    const int warp = tid >> 5;               // 0..7
    const int cta  = blockIdx.x;             // 0..127
    const int row0 = cta * 16 + warp * 2;

    // Preload weights packed as f32x2
    unsigned long long w0[16][2], w1[16][2];
#pragma unroll
    for (int k = 0; k < 16; k++) {
        float4 f0 = *(const float4*)&waa[(size_t)row0 * UNITS + k * 128 + lane * 4];
        float4 f1 = *(const float4*)&waa[(size_t)(row0 + 1) * UNITS + k * 128 + lane * 4];
        w0[k][0] = packf2(f0.x, f0.y); w0[k][1] = packf2(f0.z, f0.w);
        w1[k][0] = packf2(f1.x, f1.y); w1[k][1] = packf2(f1.z, f1.w);
    }

    for (int t = 0; t < TSTEPS; t++) {
        // lane0 prefetches this warp's xin pair (independent of the wait)
        float2 xv;
        if (lane == 0)
            xv = *(const float2*)&g_xin[(size_t)t * UNITS + row0];

        unsigned long long s01;   // packed (s0, s1)

        if (t > 0) {
            if (warp == 0) {
                const unsigned target = (unsigned)t * (unsigned)NCTA;
                while (ld_relaxed_gpu(&g_ctr) < target) { }
                fence_acq_rel_gpu();
            }
            __syncthreads();   // gate all warps on the fresh state

            // direct full-state read, pipelined into the FMA chains
            const float4* ap = (const float4*)(out + (size_t)(t - 1) * UNITS);
            unsigned long long acc0a = 0ull, acc0b = 0ull;
            unsigned long long acc1a = 0ull, acc1b = 0ull;
#pragma unroll
            for (int k = 0; k < 16; k++) {
                float4 av = ap[k * 32 + lane];
                unsigned long long pa = packf2(av.x, av.y);
                unsigned long long pb = packf2(av.z, av.w);
                acc0a = ffma2(w0[k][0], pa, acc0a);
                acc0b = ffma2(w0[k][1], pb, acc0b);
                acc1a = ffma2(w1[k][0], pa, acc1a);
                acc1b = ffma2(w1[k][1], pb, acc1b);
            }
            unsigned long long accA = addf2(acc0a, acc0b);  // (s0lo, s0hi)
            unsigned long long accB = addf2(acc1a, acc1b);  // (s1lo, s1hi)
            s01 = packf2(pair_sum(accA), pair_sum(accB));

            // packed butterfly: 5 stages, 64-bit shfl + f32x2 add
#pragma unroll
            for (int off = 16; off; off >>= 1)
                s01 = addf2(s01, __shfl_xor_sync(0xffffffffu, s01, off));
        } else {
            s01 = 0ull;        // zero initial state
        }

        if (lane == 0) {
            unsigned long long xp = packf2(xv.x, xv.y);
            unsigned long long r  = addf2(s01, xp);
            float r0, r1;
            unpackf2(r, r0, r1);
            float2 h;
            h.x = tanhf(r0);
            h.y = tanhf(r1);
            *(float2*)&out[(size_t)t * UNITS + row0] = h;
        }

        __syncthreads();   // all 16 outputs stored before the release
        if (tid == 0)
            red_release_add(&g_ctr, 1u);
    }
}

// ---------------------------------------------------------------------------
extern "C" void kernel_launch(void* const* d_in, const int* in_sizes, int n_in,
                              void* d_out, int out_size) {
    const float* x   = (const float*)d_in[0];   // (1, 8192, 512)
    const float* waa = (const float*)d_in[1];   // (2048, 2048)
    const float* wax = (const float*)d_in[2];   // (2048, 512)
    const float* ba  = (const float*)d_in[3];   // (2048, 1)
    float* out = (float*)d_out;                 // (1, 8192, 2048)

    dim3 grid(UNITS / 64, TSTEPS / 128);        // (32, 64)
    xin_gemm_kernel<<<grid, 256>>>(x, wax, ba); // also resets g_ctr

    scan_kernel<<<NCTA, SCAN_THREADS>>>(waa, out);
}